// round 16
// baseline (speedup 1.0000x reference)
#include <cuda_runtime.h>
#include <cuda_bf16.h>
#include <stdint.h>

// ---------------- constants ----------------
#define DD   128
#define HH   256
#define NMAX 50000
#define EMAX 800000
#define LMAX 3

typedef unsigned long long u64;

// ---------------- scratch ----------------
static __device__ __align__(16) float g_h[NMAX * DD];
static __device__ __align__(16) float g_A[NMAX * HH];
static __device__ __align__(16) float g_B[NMAX * HH];
static __device__ __align__(16) float g_agg[NMAX * DD];
static __device__ __align__(16) float g_gi[NMAX * 3 * DD];
static __device__ __align__(16) float g_gh[NMAX * 3 * DD];
static __device__ float g_counts[NMAX];
static __device__ int   g_src[EMAX];
static __device__ int   g_tgt[EMAX];
static __device__ int   g_mode;
static __device__ __align__(16) uint32_t g_w2img[LMAX * 65536];
static __device__ __align__(16) uint32_t g_w3img[LMAX * 32768];
static __device__ __align__(16) uint32_t g_nwimg[LMAX * 163840 + 32768];

// ---------------- helpers ----------------
__device__ __forceinline__ u64 pk2(float x, float y) {
    return ((u64)__float_as_uint(y) << 32) | (u64)__float_as_uint(x);
}
__device__ __forceinline__ float lo2(u64 v) { return __uint_as_float((unsigned)(v & 0xffffffffu)); }
__device__ __forceinline__ float hi2(u64 v) { return __uint_as_float((unsigned)(v >> 32)); }
__device__ __forceinline__ u64 fma2(u64 a, u64 b, u64 c) {
    u64 d;
    asm("fma.rn.f32x2 %0, %1, %2, %3;" : "=l"(d) : "l"(a), "l"(b), "l"(c));
    return d;
}
__device__ __forceinline__ float sigm(float x) { return 1.0f / (1.0f + expf(-x)); }

__device__ __forceinline__ float ftanh(float x) {
    float xa = fminf(fmaxf(x, -15.0f), 15.0f);
    float e = __expf(2.0f * xa);
    return __fdividef(e - 1.0f, e + 1.0f);
}

__device__ __forceinline__ uint16_t bfbits(float v) {
    __nv_bfloat16 h = __float2bfloat16(v);
    return *(uint16_t*)&h;
}
__device__ __forceinline__ float bf2f(uint16_t u) {
    return __uint_as_float(((uint32_t)u) << 16);
}
__device__ __forceinline__ uint32_t pk_bf(uint16_t a, uint16_t b) {
    return (uint32_t)a | ((uint32_t)b << 16);
}
__device__ __forceinline__ uint32_t pk_bf_f(float a, float b) {
    uint32_t r;
    asm("cvt.rn.bf16x2.f32 %0, %2, %1;" : "=r"(r) : "f"(a), "f"(b));
    return r;
}

__device__ __forceinline__ void mma_bf16(float* d, const uint32_t* a, const uint32_t* b) {
    asm volatile(
        "mma.sync.aligned.m16n8k16.row.col.f32.bf16.bf16.f32 "
        "{%0,%1,%2,%3}, {%4,%5,%6,%7}, {%8,%9}, {%0,%1,%2,%3};"
        : "+f"(d[0]), "+f"(d[1]), "+f"(d[2]), "+f"(d[3])
        : "r"(a[0]), "r"(a[1]), "r"(a[2]), "r"(a[3]), "r"(b[0]), "r"(b[1]));
}

__device__ __forceinline__ void cpa16(uint32_t saddr, const void* gaddr) {
    asm volatile("cp.async.cg.shared.global [%0], [%1], 16;" :: "r"(saddr), "l"(gaddr) : "memory");
}
#define CPA_COMMIT() asm volatile("cp.async.commit_group;" ::: "memory")
#define CPA_WAIT0()  asm volatile("cp.async.wait_group 0;" ::: "memory")

__device__ __forceinline__ uint32_t smem_to_u32(const void* p) {
    uint32_t a;
    asm("{ .reg .u64 t; cvta.to.shared.u64 t, %1; cvt.u32.u64 %0, t; }" : "=r"(a) : "l"(p));
    return a;
}

// 3-term split-bf16 mma over a group of 4 accumulators, term-major
// (dependency distance = 4 independent mmas between same-accumulator writes).
__device__ __forceinline__ void mma_group4(float (*acc)[4], const uint4* bb,
                                           const uint32_t* ah, const uint32_t* al) {
#pragma unroll
    for (int j = 0; j < 4; j++) {
        uint32_t bh[2] = {bb[j].x, bb[j].y};
        mma_bf16(acc[j], ah, bh);
    }
#pragma unroll
    for (int j = 0; j < 4; j++) {
        uint32_t bh[2] = {bb[j].x, bb[j].y};
        mma_bf16(acc[j], al, bh);
    }
#pragma unroll
    for (int j = 0; j < 4; j++) {
        uint32_t bl[2] = {bb[j].z, bb[j].w};
        mma_bf16(acc[j], ah, bl);
    }
}

// ---------------- fragment emit ----------------
__device__ __forceinline__ void frag_emit(const float* __restrict__ W, int ldw,
                                          int k0, int n, uint4* dst) {
    float v0 = W[(size_t)k0 * ldw + n];
    float v1 = W[(size_t)(k0 + 1) * ldw + n];
    float v2 = W[(size_t)(k0 + 8) * ldw + n];
    float v3 = W[(size_t)(k0 + 9) * ldw + n];
    uint16_t h0 = bfbits(v0), h1 = bfbits(v1), h2 = bfbits(v2), h3 = bfbits(v3);
    uint16_t q0 = bfbits(v0 - bf2f(h0)), q1 = bfbits(v1 - bf2f(h1));
    uint16_t q2 = bfbits(v2 - bf2f(h2)), q3 = bfbits(v3 - bf2f(h3));
    *dst = make_uint4(pk_bf(h0, h1), pk_bf(h2, h3), pk_bf(q0, q1), pk_bf(q2, q3));
}

// ---------------- launch 0: setup ----------------
__global__ void setup_kernel(const int* __restrict__ ei32,
                             const float* __restrict__ W1, const float* __restrict__ W2,
                             const float* __restrict__ W3, const float* __restrict__ Wih,
                             const float* __restrict__ Whh, const float* __restrict__ decW1,
                             float* counts, float* agg, int Nn, int E, int L) {
    int i = blockIdx.x * blockDim.x + threadIdx.x;
    if (i < Nn) counts[i] = 1.0f;
    if (i < Nn * DD) agg[i] = 0.0f;
    if (i == 0) {
        int probe = (E < 64) ? E : 64;
        int allzero = 1;
        for (int k = 0; k < probe; k++)
            if (ei32[2 * k + 1] != 0) { allzero = 0; break; }
        g_mode = allzero;
    }
    int lane = i & 31;
    int t = i >> 5;
    const int w2t = L * 512, w3t = L * 256, ndt = L * 1280;
    if (t < w2t) {
        int l = t / 512, tile = t % 512;
        int ntl = tile & 7, kt = (tile >> 3) & 15, c = tile >> 7;
        int n = c * 64 + ntl * 8 + (lane >> 2);
        int k0 = kt * 16 + (lane & 3) * 2;
        frag_emit(W2 + (size_t)l * 65536, 256, k0, n,
                  (uint4*)(g_w2img + (size_t)l * 65536 + tile * 128) + lane);
        return;
    }
    t -= w2t;
    if (t < w3t) {
        int l = t / 256, tile = t % 256;
        int ntl = tile & 15, kt2 = (tile >> 4) & 3, c = tile >> 6;
        int n = ntl * 8 + (lane >> 2);
        int k0 = c * 64 + kt2 * 16 + (lane & 3) * 2;
        frag_emit(W3 + (size_t)l * 32768, 128, k0, n,
                  (uint4*)(g_w3img + (size_t)l * 32768 + tile * 128) + lane);
        return;
    }
    t -= w3t;
    if (t < ndt) {
        int l = t / 1280, tile = t % 1280;
        const float* W;
        int N;
        uint32_t* out;
        int toff;
        if (tile < 256)      { W = W1 + (size_t)l * 65536;          N = 256; out = g_nwimg + (size_t)l * 163840;          toff = tile; }
        else if (tile < 512) { W = W1 + (size_t)l * 65536 + 32768;  N = 256; out = g_nwimg + (size_t)l * 163840 + 32768;  toff = tile - 256; }
        else if (tile < 896) { W = Wih + (size_t)l * 49152;         N = 384; out = g_nwimg + (size_t)l * 163840 + 65536;  toff = tile - 512; }
        else                 { W = Whh + (size_t)l * 49152;         N = 384; out = g_nwimg + (size_t)l * 163840 + 114688; toff = tile - 896; }
        int ntl = toff & 15, kt = (toff >> 4) & 7, c = toff >> 7;
        int n = c * 128 + ntl * 8 + (lane >> 2);
        int k0 = kt * 16 + (lane & 3) * 2;
        frag_emit(W, N, k0, n, (uint4*)(out + toff * 128) + lane);
        return;
    }
    t -= ndt;
    if (t < 256) {
        int ntl = t & 15, kt = (t >> 4) & 7, c = t >> 7;
        int n = c * 128 + ntl * 8 + (lane >> 2);
        int k0 = kt * 16 + (lane & 3) * 2;
        frag_emit(decW1, 256, k0, n,
                  (uint4*)(g_nwimg + (size_t)L * 163840 + t * 128) + lane);
    }
}

// ---------------- tiny utility kernels ----------------
__global__ void gru_gate(const float* __restrict__ gi, const float* __restrict__ gh,
                         float* h, float* agg, int Nn) {
    int idx = blockIdx.x * blockDim.x + threadIdx.x;
    if (idx < Nn * DD) {
        int i = idx >> 7, c = idx & 127;
        size_t base = (size_t)i * (3 * DD);
        float r = sigm(gi[base + c] + gh[base + c]);
        float z = sigm(gi[base + DD + c] + gh[base + DD + c]);
        float n = tanhf(gi[base + 2 * DD + c] + r * gh[base + 2 * DD + c]);
        float hv = h[idx];
        h[idx] = (1.0f - z) * n + z * hv;
        agg[idx] = 0.0f;
    }
}
__global__ void dec_final(const float* __restrict__ o2, const float* __restrict__ W3,
                          const float* __restrict__ b3, float* __restrict__ out, int Nn) {
    int gid = blockIdx.x * blockDim.x + threadIdx.x;
    int node = gid >> 5, lane = gid & 31;
    if (node >= Nn) return;
    float s = 0.0f;
    const float* row = o2 + (size_t)node * 256;
#pragma unroll
    for (int j = 0; j < 8; j++) s += row[lane + 32 * j] * W3[lane + 32 * j];
#pragma unroll
    for (int off = 16; off > 0; off >>= 1) s += __shfl_down_sync(0xffffffffu, s, off);
    if (lane == 0) out[node] = s + b3[0];
}

// ---------------- fp32 tiled GEMM (encoder K=16, dec_W2 K=256) ----------------
template <int N, int K, bool DOTANH>
__global__ void gemm_kernel(const float* __restrict__ A, const float* __restrict__ W,
                            const float* __restrict__ bias, float* __restrict__ out, int M) {
    constexpr int BM = 32;
    constexpr int NC = N / 4;
    constexpr int K4 = K / 4;
    constexpr int STR = BM + 2;
    __shared__ float s_a[K * STR];

    const int row0 = blockIdx.x * BM;
    const int tid = threadIdx.x;

    for (int idx = tid; idx < BM * K4; idx += N) {
        int r = idx / K4, k4 = idx % K4;
        float4 v = make_float4(0.f, 0.f, 0.f, 0.f);
        int row = row0 + r;
        if (row < M) v = reinterpret_cast<const float4*>(A)[(size_t)row * K4 + k4];
        s_a[(4 * k4 + 0) * STR + r] = v.x;
        s_a[(4 * k4 + 1) * STR + r] = v.y;
        s_a[(4 * k4 + 2) * STR + r] = v.z;
        s_a[(4 * k4 + 3) * STR + r] = v.w;
    }
    __syncthreads();

    const int colg = tid % NC;
    const int rg = tid / NC;
    const int r0 = rg * 8;

    u64 acc[4][4];
#pragma unroll
    for (int c = 0; c < 4; c++)
#pragma unroll
        for (int p = 0; p < 4; p++) acc[c][p] = 0ull;

    const float4* W4 = reinterpret_cast<const float4*>(W);
    for (int k = 0; k < K; k++) {
        float4 w = W4[(size_t)k * NC + colg];
        u64 w0 = pk2(w.x, w.x), w1 = pk2(w.y, w.y), w2 = pk2(w.z, w.z), w3 = pk2(w.w, w.w);
        const float* srow = &s_a[k * STR + r0];
#pragma unroll
        for (int p = 0; p < 4; p++) {
            u64 m = *reinterpret_cast<const u64*>(srow + 2 * p);
            acc[0][p] = fma2(m, w0, acc[0][p]);
            acc[1][p] = fma2(m, w1, acc[1][p]);
            acc[2][p] = fma2(m, w2, acc[2][p]);
            acc[3][p] = fma2(m, w3, acc[3][p]);
        }
    }

    float4 bv = make_float4(0.f, 0.f, 0.f, 0.f);
    if (bias) bv = reinterpret_cast<const float4*>(bias)[colg];

#pragma unroll
    for (int p = 0; p < 4; p++) {
#pragma unroll
        for (int hh = 0; hh < 2; hh++) {
            int row = row0 + r0 + 2 * p + hh;
            if (row < M) {
                float4 o;
                o.x = (hh ? hi2(acc[0][p]) : lo2(acc[0][p])) + bv.x;
                o.y = (hh ? hi2(acc[1][p]) : lo2(acc[1][p])) + bv.y;
                o.z = (hh ? hi2(acc[2][p]) : lo2(acc[2][p])) + bv.z;
                o.w = (hh ? hi2(acc[3][p]) : lo2(acc[3][p])) + bv.w;
                if (DOTANH) { o.x = tanhf(o.x); o.y = tanhf(o.y); o.z = tanhf(o.z); o.w = tanhf(o.w); }
                reinterpret_cast<float4*>(out)[(size_t)row * NC + colg] = o;
            }
        }
    }
}

// ---------------- split-bf16 mma node GEMM (kt double buffer + term-major groups) ------
template <int N, bool DOTANH, bool MEANB3>
__global__ void __launch_bounds__(256, 1)
gemm_mma(const float* __restrict__ A, const uint32_t* __restrict__ Wimg,
         const float* __restrict__ bias, float* __restrict__ out, int M,
         const float* __restrict__ counts, const float* __restrict__ cb3) {
    constexpr int NCH = N / 128;
    extern __shared__ char smem[];
    uint32_t* ahi = (uint32_t*)smem;
    uint32_t* alo = (uint32_t*)(smem + 32768);
    uint32_t* wb  = (uint32_t*)(smem + 65536);
    float* sbias  = (float*)(smem + 196608);
    const uint32_t sb = smem_to_u32(smem);

    const int tid = threadIdx.x, wid = tid >> 5, lid = tid & 31;
    const int row0 = blockIdx.x * 128;

    {
        const char* src = (const char*)Wimg + tid * 16;
        uint32_t dst = sb + 65536 + tid * 16;
#pragma unroll
        for (int j = 0; j < 16; j++) cpa16(dst + j * 4096, src + j * 4096);
        CPA_COMMIT();
    }
    for (int i = tid; i < N; i += 256) sbias[i] = bias[i];

    {
        const int e = tid >> 1, half = tid & 1;
        const int row = row0 + e;
        const float4* Ar = reinterpret_cast<const float4*>(A) + (size_t)row * 32 + half * 16;
        const int rb = e * 64;
        const int es = (e & 7) << 2;
        float cn = 1.0f;
        if (MEANB3 && row < M) cn = __fdividef(1.0f, counts[row]);
#pragma unroll 4
        for (int i = 0; i < 16; i++) {
            float4 a = (row < M) ? Ar[i] : make_float4(0.f, 0.f, 0.f, 0.f);
            if (MEANB3) {
                float4 bv = reinterpret_cast<const float4*>(cb3)[half * 16 + i];
                a.x = a.x * cn + bv.x;
                a.y = a.y * cn + bv.y;
                a.z = a.z * cn + bv.z;
                a.w = a.w * cn + bv.w;
            }
            uint16_t h0 = bfbits(a.x), h1 = bfbits(a.y), h2 = bfbits(a.z), h3 = bfbits(a.w);
            const int w = half * 32 + i * 2;
            const int sw = w ^ es;
            asm volatile("st.shared.v2.b32 [%0], {%1, %2};" ::
                         "r"(sb + (rb + sw) * 4),
                         "r"(pk_bf(h0, h1)), "r"(pk_bf(h2, h3)) : "memory");
            asm volatile("st.shared.v2.b32 [%0], {%1, %2};" ::
                         "r"(sb + 32768 + (rb + sw) * 4),
                         "r"(pk_bf_f(a.x - bf2f(h0), a.y - bf2f(h1))),
                         "r"(pk_bf_f(a.z - bf2f(h2), a.w - bf2f(h3))) : "memory");
        }
    }

    const int g = lid >> 2, q = lid & 3;
    const int r0 = wid * 16 + g;
    const int rowA = r0 * 64, rowB = (r0 + 8) * 64, sswz = g << 2;

    uint32_t ahp[2][4], alp[2][4];

    for (int c = 0; c < NCH; c++) {
        CPA_WAIT0();
        __syncthreads();
        if (c == 0) {
            const int swA = q ^ sswz, swB = (q + 4) ^ sswz;
            ahp[0][0] = ahi[rowA + swA];  ahp[0][1] = ahi[rowB + swA];
            ahp[0][2] = ahi[rowA + swB];  ahp[0][3] = ahi[rowB + swB];
            alp[0][0] = alo[rowA + swA];  alp[0][1] = alo[rowB + swA];
            alp[0][2] = alo[rowA + swB];  alp[0][3] = alo[rowB + swB];
        }
        if (c + 1 < NCH) {
            const char* src = (const char*)(Wimg + (c + 1) * 16384) + tid * 16;
            uint32_t dst = sb + 65536 + ((c + 1) & 1) * 65536 + tid * 16;
#pragma unroll
            for (int j = 0; j < 16; j++) cpa16(dst + j * 4096, src + j * 4096);
            CPA_COMMIT();
        }
        const uint32_t* wc = wb + (c & 1) * 16384;

        float s2[16][4];
#pragma unroll
        for (int n = 0; n < 16; n++)
#pragma unroll
            for (int p = 0; p < 4; p++) s2[n][p] = 0.0f;

        for (int kt = 0; kt < 8; kt++) {
            const int cur = kt & 1;
            {
                const int w0 = ((kt + 1) & 7) * 8 + q;
                const int swA = w0 ^ sswz, swB = (w0 + 4) ^ sswz;
                ahp[cur ^ 1][0] = ahi[rowA + swA];  ahp[cur ^ 1][1] = ahi[rowB + swA];
                ahp[cur ^ 1][2] = ahi[rowA + swB];  ahp[cur ^ 1][3] = ahi[rowB + swB];
                alp[cur ^ 1][0] = alo[rowA + swA];  alp[cur ^ 1][1] = alo[rowB + swA];
                alp[cur ^ 1][2] = alo[rowA + swB];  alp[cur ^ 1][3] = alo[rowB + swB];
            }
#pragma unroll
            for (int ng = 0; ng < 4; ng++) {
                uint4 bb[4];
#pragma unroll
                for (int j = 0; j < 4; j++)
                    bb[j] = *reinterpret_cast<const uint4*>(
                        wc + (kt * 16 + ng * 4 + j) * 128 + lid * 4);
                mma_group4(&s2[ng * 4], bb, ahp[cur], alp[cur]);
            }
        }

        const int ra = row0 + r0, rb2 = ra + 8;
#pragma unroll
        for (int nt = 0; nt < 16; nt++) {
            const int col = c * 128 + nt * 8 + 2 * q;
            const float b0v = sbias[col], b1v = sbias[col + 1];
            float o0 = s2[nt][0] + b0v, o1 = s2[nt][1] + b1v;
            float o2v = s2[nt][2] + b0v, o3 = s2[nt][3] + b1v;
            if (DOTANH) { o0 = ftanh(o0); o1 = ftanh(o1); o2v = ftanh(o2v); o3 = ftanh(o3); }
            if (ra < M) *reinterpret_cast<float2*>(out + (size_t)ra * N + col) = make_float2(o0, o1);
            if (rb2 < M) *reinterpret_cast<float2*>(out + (size_t)rb2 * N + col) = make_float2(o2v, o3);
        }
    }
}

// ---------------- gemm_dual: A/B precompute fused + convert ----------------
__global__ void __launch_bounds__(256, 1)
gemm_dual(const float* __restrict__ Ain, const uint32_t* __restrict__ Wimg,
          const float* __restrict__ b1, float* __restrict__ outA, float* __restrict__ outB,
          int M, int nG, const void* __restrict__ ei, float* counts, int E, int do_convert) {
    if (blockIdx.x >= nG) {
        if (!do_convert) return;
        int base = (blockIdx.x - nG) * 2048 + threadIdx.x;
        const int mode = g_mode;
#pragma unroll
        for (int j = 0; j < 8; j++) {
            int e = base + j * 256;
            if (e < E) {
                int s, t;
                if (mode) {
                    const long long* p = (const long long*)ei;
                    s = (int)p[e];
                    t = (int)p[(size_t)E + e];
                } else {
                    const int* p = (const int*)ei;
                    s = p[e];
                    t = p[E + e];
                }
                g_src[e] = s;
                g_tgt[e] = t;
                atomicAdd(&counts[t], 1.0f);
            }
        }
        return;
    }

    extern __shared__ char smem[];
    uint32_t* ahi = (uint32_t*)smem;
    uint32_t* alo = (uint32_t*)(smem + 32768);
    uint32_t* wb  = (uint32_t*)(smem + 65536);
    float* sbias  = (float*)(smem + 196608);
    const uint32_t sb = smem_to_u32(smem);

    const int tid = threadIdx.x, wid = tid >> 5, lid = tid & 31;
    const int row0 = blockIdx.x * 128;

    {
        const char* src = (const char*)Wimg + tid * 16;
        uint32_t dst = sb + 65536 + tid * 16;
#pragma unroll
        for (int j = 0; j < 16; j++) cpa16(dst + j * 4096, src + j * 4096);
        CPA_COMMIT();
    }
    sbias[tid] = b1[tid];

    {
        const int e = tid >> 1, half = tid & 1;
        const int row = row0 + e;
        const float4* Ar = reinterpret_cast<const float4*>(Ain) + (size_t)row * 32 + half * 16;
        const int rb = e * 64;
        const int es = (e & 7) << 2;
#pragma unroll 4
        for (int i = 0; i < 16; i++) {
            float4 a = (row < M) ? Ar[i] : make_float4(0.f, 0.f, 0.f, 0.f);
            uint16_t h0 = bfbits(a.x), h1 = bfbits(a.y), h2 = bfbits(a.z), h3 = bfbits(a.w);
            const int w = half * 32 + i * 2;
            const int sw = w ^ es;
            asm volatile("st.shared.v2.b32 [%0], {%1, %2};" ::
                         "r"(sb + (rb + sw) * 4),
                         "r"(pk_bf(h0, h1)), "r"(pk_bf(h2, h3)) : "memory");
            asm volatile("st.shared.v2.b32 [%0], {%1, %2};" ::
                         "r"(sb + 32768 + (rb + sw) * 4),
                         "r"(pk_bf_f(a.x - bf2f(h0), a.y - bf2f(h1))),
                         "r"(pk_bf_f(a.z - bf2f(h2), a.w - bf2f(h3))) : "memory");
        }
    }

    const int g = lid >> 2, q = lid & 3;
    const int r0 = wid * 16 + g;
    const int rowA = r0 * 64, rowB = (r0 + 8) * 64, sswz = g << 2;

    uint32_t ahp[2][4], alp[2][4];

    for (int c = 0; c < 4; c++) {
        CPA_WAIT0();
        __syncthreads();
        if (c == 0) {
            const int swA = q ^ sswz, swB = (q + 4) ^ sswz;
            ahp[0][0] = ahi[rowA + swA];  ahp[0][1] = ahi[rowB + swA];
            ahp[0][2] = ahi[rowA + swB];  ahp[0][3] = ahi[rowB + swB];
            alp[0][0] = alo[rowA + swA];  alp[0][1] = alo[rowB + swA];
            alp[0][2] = alo[rowA + swB];  alp[0][3] = alo[rowB + swB];
        }
        if (c < 3) {
            const char* src = (const char*)(Wimg + (c + 1) * 16384) + tid * 16;
            uint32_t dst = sb + 65536 + ((c + 1) & 1) * 65536 + tid * 16;
#pragma unroll
            for (int j = 0; j < 16; j++) cpa16(dst + j * 4096, src + j * 4096);
            CPA_COMMIT();
        }
        const uint32_t* wc = wb + (c & 1) * 16384;

        float s2[16][4];
#pragma unroll
        for (int n = 0; n < 16; n++)
#pragma unroll
            for (int p = 0; p < 4; p++) s2[n][p] = 0.0f;

        for (int kt = 0; kt < 8; kt++) {
            const int cur = kt & 1;
            {
                const int w0 = ((kt + 1) & 7) * 8 + q;
                const int swA = w0 ^ sswz, swB = (w0 + 4) ^ sswz;
                ahp[cur ^ 1][0] = ahi[rowA + swA];  ahp[cur ^ 1][1] = ahi[rowB + swA];
                ahp[cur ^ 1][2] = ahi[rowA + swB];  ahp[cur ^ 1][3] = ahi[rowB + swB];
                alp[cur ^ 1][0] = alo[rowA + swA];  alp[cur ^ 1][1] = alo[rowB + swA];
                alp[cur ^ 1][2] = alo[rowA + swB];  alp[cur ^ 1][3] = alo[rowB + swB];
            }
#pragma unroll
            for (int ng = 0; ng < 4; ng++) {
                uint4 bb[4];
#pragma unroll
                for (int j = 0; j < 4; j++)
                    bb[j] = *reinterpret_cast<const uint4*>(
                        wc + (kt * 16 + ng * 4 + j) * 128 + lid * 4);
                mma_group4(&s2[ng * 4], bb, ahp[cur], alp[cur]);
            }
        }

        float* out = (c < 2) ? outA : outB;
        const int cc = c & 1;
        const bool addb = (c < 2);
        const int ra = row0 + r0, rb2 = ra + 8;
#pragma unroll
        for (int nt = 0; nt < 16; nt++) {
            const int col = cc * 128 + nt * 8 + 2 * q;
            float b0v = addb ? sbias[col] : 0.0f;
            float b1v = addb ? sbias[col + 1] : 0.0f;
            float o0 = s2[nt][0] + b0v, o1 = s2[nt][1] + b1v;
            float o2v = s2[nt][2] + b0v, o3 = s2[nt][3] + b1v;
            if (ra < M) *reinterpret_cast<float2*>(out + (size_t)ra * HH + col) = make_float2(o0, o1);
            if (rb2 < M) *reinterpret_cast<float2*>(out + (size_t)rb2 * HH + col) = make_float2(o2v, o3);
        }
    }
}

// ---------------- persistent mma.sync fused edge kernel (term-major mma groups) --------
#define TEM 128
#define SM2_TGT   0
#define SM2_B2    512
#define SM2_M1HI  2048
#define SM2_M1LO  (SM2_M1HI + 65536)
#define SM2_W2    (SM2_M1LO + 65536)
#define SM2_W3    (SM2_W2 + 65536)
#define SM2_TOTAL (SM2_W3 + 32768)       // 231424 bytes

__global__ void __launch_bounds__(256, 1)
edge_mma_kernel(const float* __restrict__ Abuf, const float* __restrict__ Bbuf,
                const uint32_t* __restrict__ w2img, const uint32_t* __restrict__ w3img,
                const float* __restrict__ b2,
                float* __restrict__ agg, int E, int Nn, int ntiles) {
    extern __shared__ char smem[];
    int* s_tgt = (int*)(smem + SM2_TGT);
    float* s_b2 = (float*)(smem + SM2_B2);
    const uint32_t* m1hi = (const uint32_t*)(smem + SM2_M1HI);
    const uint32_t* m1lo = (const uint32_t*)(smem + SM2_M1LO);
    const uint32_t* w2buf = (const uint32_t*)(smem + SM2_W2);
    const uint32_t* w3buf = (const uint32_t*)(smem + SM2_W3);
    const uint32_t sb = smem_to_u32(smem);

    const int tid = threadIdx.x;
    const int wid = tid >> 5, lid = tid & 31;
    const int total = E + Nn;

    {
        const char* src = (const char*)w2img + tid * 16;
        uint32_t dst = sb + SM2_W2 + tid * 16;
#pragma unroll
        for (int j = 0; j < 16; j++) cpa16(dst + j * 4096, src + j * 4096);
        CPA_COMMIT();
    }
    s_b2[tid] = b2[tid];

    const int g = lid >> 2;
    const int q = lid & 3;
    const int r0w = wid * 16 + g;
    const int sswz = g << 2;
    const int rowA = r0w * 128, rowB = (r0w + 8) * 128;

    for (int tile = blockIdx.x; tile < ntiles; tile += gridDim.x) {
        // ---- stage 1: gather + tanh + split ----
        {
            const int e = tid >> 1, half = tid & 1;
            const int eid = tile * TEM + e;
            int si = 0, ti = 0;
            const bool valid = (eid < total);
            if (valid) {
                if (eid < E) { si = g_src[eid]; ti = g_tgt[eid]; }
                else         { si = ti = eid - E; }
            }
            if (half == 0) s_tgt[e] = valid ? ti : -1;
            const float4* Ar = reinterpret_cast<const float4*>(Abuf) + (size_t)ti * 64;
            const float4* Br = reinterpret_cast<const float4*>(Bbuf) + (size_t)si * 64;
            const int rb = e * 128;
            const int es = (e & 7) << 2;
#pragma unroll 8
            for (int i = 0; i < 32; i++) {
                float4 a = Ar[half * 32 + i], b = Br[half * 32 + i];
                float v0 = ftanh(a.x + b.x), v1 = ftanh(a.y + b.y);
                float v2 = ftanh(a.z + b.z), v3 = ftanh(a.w + b.w);
                uint16_t h0 = bfbits(v0), h1 = bfbits(v1), h2 = bfbits(v2), h3 = bfbits(v3);
                const int w = half * 64 + i * 2;
                const int sw = w ^ es;
                asm volatile("st.shared.v2.b32 [%0], {%1, %2};" ::
                             "r"(sb + SM2_M1HI + (rb + sw) * 4),
                             "r"(pk_bf(h0, h1)), "r"(pk_bf(h2, h3)) : "memory");
                asm volatile("st.shared.v2.b32 [%0], {%1, %2};" ::
                             "r"(sb + SM2_M1LO + (rb + sw) * 4),
                             "r"(pk_bf_f(v0 - bf2f(h0), v1 - bf2f(h1))),
                             "r"(pk_bf_f(v2 - bf2f(h2), v3 - bf2f(h3))) : "memory");
            }
        }

        float m3[16][4];
#pragma unroll
        for (int n = 0; n < 16; n++)
#pragma unroll
            for (int p = 0; p < 4; p++) m3[n][p] = 0.0f;

        int tg0 = -1, tg1 = -1;
        uint32_t ahf[2][4], alf[2][4];

        for (int c = 0; c < 4; c++) {
            CPA_WAIT0();
            __syncthreads();

            if (c == 0) {
                tg0 = s_tgt[r0w];
                tg1 = s_tgt[r0w + 8];
                const int swA = q ^ sswz, swB = (q + 4) ^ sswz;
                ahf[0][0] = m1hi[rowA + swA];  ahf[0][1] = m1hi[rowB + swA];
                ahf[0][2] = m1hi[rowA + swB];  ahf[0][3] = m1hi[rowB + swB];
                alf[0][0] = m1lo[rowA + swA];  alf[0][1] = m1lo[rowB + swA];
                alf[0][2] = m1lo[rowA + swB];  alf[0][3] = m1lo[rowB + swB];
            }

            // prefetch W3 chunk c (overlaps stage 2)
            {
                const char* src = (const char*)(w3img + c * 8192) + tid * 16;
                uint32_t dst = sb + SM2_W3 + tid * 16;
#pragma unroll
                for (int j = 0; j < 4; j++) cpa16(dst + j * 4096, src + j * 4096);
#pragma unroll
                for (int j = 4; j < 8; j++) cpa16(dst + j * 4096, src + j * 4096);
                CPA_COMMIT();
            }

            // ---- stage 2: term-major mma groups ----
            float s2[8][4];
#pragma unroll
            for (int n = 0; n < 8; n++)
#pragma unroll
                for (int p = 0; p < 4; p++) s2[n][p] = 0.0f;

            for (int kt = 0; kt < 16; kt++) {
                const int cur = kt & 1;
                {
                    const int w0 = ((kt + 1) & 15) * 8 + q;
                    const int swA = w0 ^ sswz, swB = (w0 + 4) ^ sswz;
                    ahf[cur ^ 1][0] = m1hi[rowA + swA];  ahf[cur ^ 1][1] = m1hi[rowB + swA];
                    ahf[cur ^ 1][2] = m1hi[rowA + swB];  ahf[cur ^ 1][3] = m1hi[rowB + swB];
                    alf[cur ^ 1][0] = m1lo[rowA + swA];  alf[cur ^ 1][1] = m1lo[rowB + swA];
                    alf[cur ^ 1][2] = m1lo[rowA + swB];  alf[cur ^ 1][3] = m1lo[rowB + swB];
                }
#pragma unroll
                for (int ng = 0; ng < 2; ng++) {
                    uint4 bb[4];
#pragma unroll
                    for (int j = 0; j < 4; j++)
                        bb[j] = *reinterpret_cast<const uint4*>(
                            w2buf + (kt * 8 + ng * 4 + j) * 128 + lid * 4);
                    mma_group4(&s2[ng * 4], bb, ahf[cur], alf[cur]);
                }
            }

            // ---- epilogue: tanh(+b2), split -> stage-3 A fragments ----
            uint32_t a2hi[4][4], a2lo[4][4];
#pragma unroll
            for (int nt = 0; nt < 8; nt++) {
                const int colbase = c * 64 + nt * 8 + 2 * q;
                const float b0v = s_b2[colbase], b1v = s_b2[colbase + 1];
                float v0 = ftanh(s2[nt][0] + b0v), v1 = ftanh(s2[nt][1] + b1v);
                float v2 = ftanh(s2[nt][2] + b0v), v3 = ftanh(s2[nt][3] + b1v);
                uint16_t h0 = bfbits(v0), h1 = bfbits(v1), h2 = bfbits(v2), h3 = bfbits(v3);
                const int t2 = nt >> 1, ko = (nt & 1) * 2;
                a2hi[t2][ko + 0] = pk_bf(h0, h1);
                a2hi[t2][ko + 1] = pk_bf(h2, h3);
                a2lo[t2][ko + 0] = pk_bf_f(v0 - bf2f(h0), v1 - bf2f(h1));
                a2lo[t2][ko + 1] = pk_bf_f(v2 - bf2f(h2), v3 - bf2f(h3));
            }

            CPA_WAIT0();
            __syncthreads();

            // prefetch W2 next chunk (wraps to chunk 0 for the next tile)
            if (c < 3 || tile + gridDim.x < ntiles) {
                const int cn = (c + 1) & 3;
                const char* src = (const char*)(w2img + cn * 16384) + tid * 16;
                uint32_t dst = sb + SM2_W2 + tid * 16;
#pragma unroll
                for (int j = 0; j < 16; j++) cpa16(dst + j * 4096, src + j * 4096);
                CPA_COMMIT();
            }

            // ---- stage 3: term-major mma groups over 16 nt ----
            for (int kt2 = 0; kt2 < 4; kt2++) {
#pragma unroll
                for (int ng = 0; ng < 4; ng++) {
                    uint4 bb[4];
#pragma unroll
                    for (int j = 0; j < 4; j++)
                        bb[j] = *reinterpret_cast<const uint4*>(
                            w3buf + (kt2 * 16 + ng * 4 + j) * 128 + lid * 4);
                    mma_group4(&m3[ng * 4], bb, a2hi[kt2], a2lo[kt2]);
                }
            }
        }

        // ---- scatter ----
        if (tg0 >= 0) {
            float2* base = reinterpret_cast<float2*>(agg + (size_t)tg0 * DD + 2 * q);
#pragma unroll
            for (int nt = 0; nt < 16; nt++)
                atomicAdd(base + nt * 4, make_float2(m3[nt][0], m3[nt][1]));
        }
        if (tg1 >= 0) {
            float2* base = reinterpret_cast<float2*>(agg + (size_t)tg1 * DD + 2 * q);
#pragma unroll
            for (int nt = 0; nt < 16; nt++)
                atomicAdd(base + nt * 4, make_float2(m3[nt][2], m3[nt][3]));
        }
    }
}

// ---------------- host launcher ----------------
extern "C" void kernel_launch(void* const* d_in, const int* in_sizes, int n_in,
                              void* d_out, int out_size) {
    const float* x      = (const float*)d_in[0];
    const void*  ei     = d_in[1];
    const float* enc_W  = (const float*)d_in[2];
    const float* enc_b  = (const float*)d_in[3];
    const float* msg_W1 = (const float*)d_in[4];
    const float* msg_b1 = (const float*)d_in[5];
    const float* msg_W2 = (const float*)d_in[6];
    const float* msg_b2 = (const float*)d_in[7];
    const float* msg_W3 = (const float*)d_in[8];
    const float* msg_b3 = (const float*)d_in[9];
    const float* gru_Wih = (const float*)d_in[10];
    const float* gru_Whh = (const float*)d_in[11];
    const float* gru_bih = (const float*)d_in[12];
    const float* gru_bhh = (const float*)d_in[13];
    const float* dec_W1 = (const float*)d_in[14];
    const float* dec_b1 = (const float*)d_in[15];
    const float* dec_W2 = (const float*)d_in[16];
    const float* dec_b2 = (const float*)d_in[17];
    const float* dec_W3 = (const float*)d_in[18];
    const float* dec_b3 = (const float*)d_in[19];

    const int Nn = in_sizes[0] / 16;
    const int E  = in_sizes[1] / 2;
    const int L  = in_sizes[4] / (2 * DD * HH);

    float *h, *A, *B, *agg, *gi, *gh, *counts;
    uint32_t *w2img, *w3img, *nwimg;
    cudaGetSymbolAddress((void**)&h, g_h);
    cudaGetSymbolAddress((void**)&A, g_A);
    cudaGetSymbolAddress((void**)&B, g_B);
    cudaGetSymbolAddress((void**)&agg, g_agg);
    cudaGetSymbolAddress((void**)&gi, g_gi);
    cudaGetSymbolAddress((void**)&gh, g_gh);
    cudaGetSymbolAddress((void**)&counts, g_counts);
    cudaGetSymbolAddress((void**)&w2img, g_w2img);
    cudaGetSymbolAddress((void**)&w3img, g_w3img);
    cudaGetSymbolAddress((void**)&nwimg, g_nwimg);

    cudaFuncSetAttribute(edge_mma_kernel, cudaFuncAttributeMaxDynamicSharedMemorySize,
                         SM2_TOTAL);
    cudaFuncSetAttribute(gemm_dual, cudaFuncAttributeMaxDynamicSharedMemorySize,
                         196608 + 1024);
    cudaFuncSetAttribute(gemm_mma<256, true, false>, cudaFuncAttributeMaxDynamicSharedMemorySize,
                         196608 + 256 * 4);
    cudaFuncSetAttribute(gemm_mma<384, false, false>, cudaFuncAttributeMaxDynamicSharedMemorySize,
                         196608 + 384 * 4);
    cudaFuncSetAttribute(gemm_mma<384, false, true>, cudaFuncAttributeMaxDynamicSharedMemorySize,
                         196608 + 384 * 4);

    int dev = 0;
    cudaGetDevice(&dev);
    int nsm = 148;
    cudaDeviceGetAttribute(&nsm, cudaDevAttrMultiProcessorCount, dev);

    const int gM = (Nn + 31) / 32;
    const int gM2 = (Nn + 127) / 128;
    const int ntiles = (E + Nn + TEM - 1) / TEM;
    const int nConv = (E + 2047) / 2048;
    const int smn256 = 196608 + 256 * 4;
    const int smn384 = 196608 + 384 * 4;
    const int smdual = 196608 + 1024;

    setup_kernel<<<(Nn * DD + 255) / 256, 256>>>(
        (const int*)ei, msg_W1, msg_W2, msg_W3, gru_Wih, gru_Whh, dec_W1,
        counts, agg, Nn, E, L);
    gemm_kernel<128, 16, true><<<gM, 128>>>(x, enc_W, enc_b, h, Nn);

    for (int l = 0; l < L; l++) {
        const uint32_t* img = nwimg + (size_t)l * 163840;
        const float* b1l = msg_b1 + (size_t)l * HH;
        const float* b2l = msg_b2 + (size_t)l * HH;
        const float* b3l = msg_b3 + (size_t)l * DD;
        const float* bih = gru_bih + (size_t)l * 3 * DD;
        const float* bhh = gru_bhh + (size_t)l * 3 * DD;

        gemm_dual<<<gM2 + nConv, 256, smdual>>>(
            h, img, b1l, A, B, Nn, gM2, ei, counts, E, l == 0 ? 1 : 0);

        edge_mma_kernel<<<nsm, 256, SM2_TOTAL>>>(
            A, B, w2img + (size_t)l * 65536, w3img + (size_t)l * 32768,
            b2l, agg, E, Nn, ntiles);

        gemm_mma<384, false, true><<<gM2, 256, smn384>>>(agg, img + 65536, bih, gi, Nn,
                                                         counts, b3l);
        gemm_mma<384, false, false><<<gM2, 256, smn384>>>(h, img + 114688, bhh, gh, Nn,
                                                          nullptr, nullptr);
        gru_gate<<<(Nn * DD + 255) / 256, 256>>>(gi, gh, h, agg, Nn);
    }

    gemm_mma<256, true, false><<<gM2, 256, smn256>>>(h, nwimg + (size_t)L * 163840, dec_b1,
                                                     A, Nn, nullptr, nullptr);
    gemm_kernel<256, 256, true><<<gM, 256>>>(A, dec_W2, dec_b2, B, Nn);
    dec_final<<<(Nn + 7) / 8, 256>>>(B, dec_W3, dec_b3, (float*)d_out, Nn);
}

// round 17
// speedup vs baseline: 1.1981x; 1.1981x over previous
#include <cuda_runtime.h>
#include <cuda_bf16.h>
#include <stdint.h>

// ---------------- constants ----------------
#define DD   128
#define HH   256
#define NMAX 50000
#define EMAX 800000
#define LMAX 3

typedef unsigned long long u64;

// ---------------- scratch ----------------
static __device__ __align__(16) float g_h[NMAX * DD];
static __device__ __align__(16) float g_A[NMAX * HH];
static __device__ __align__(16) float g_B[NMAX * HH];
static __device__ __align__(16) float g_agg[NMAX * DD];
static __device__ __align__(16) float g_gi[NMAX * 3 * DD];
static __device__ __align__(16) float g_gh[NMAX * 3 * DD];
static __device__ float g_counts[NMAX];
static __device__ int   g_src[EMAX];
static __device__ int   g_tgt[EMAX];
static __device__ int   g_mode;
static __device__ __align__(16) uint32_t g_w2img[LMAX * 65536];
static __device__ __align__(16) uint32_t g_w3img[LMAX * 32768];
static __device__ __align__(16) uint32_t g_nwimg[LMAX * 163840 + 32768];

// ---------------- helpers ----------------
__device__ __forceinline__ u64 pk2(float x, float y) {
    return ((u64)__float_as_uint(y) << 32) | (u64)__float_as_uint(x);
}
__device__ __forceinline__ float lo2(u64 v) { return __uint_as_float((unsigned)(v & 0xffffffffu)); }
__device__ __forceinline__ float hi2(u64 v) { return __uint_as_float((unsigned)(v >> 32)); }
__device__ __forceinline__ u64 fma2(u64 a, u64 b, u64 c) {
    u64 d;
    asm("fma.rn.f32x2 %0, %1, %2, %3;" : "=l"(d) : "l"(a), "l"(b), "l"(c));
    return d;
}
__device__ __forceinline__ float sigm(float x) { return 1.0f / (1.0f + expf(-x)); }

__device__ __forceinline__ float ftanh(float x) {
    float xa = fminf(fmaxf(x, -15.0f), 15.0f);
    float e = __expf(2.0f * xa);
    return __fdividef(e - 1.0f, e + 1.0f);
}

__device__ __forceinline__ uint16_t bfbits(float v) {
    __nv_bfloat16 h = __float2bfloat16(v);
    return *(uint16_t*)&h;
}
__device__ __forceinline__ float bf2f(uint16_t u) {
    return __uint_as_float(((uint32_t)u) << 16);
}
__device__ __forceinline__ uint32_t pk_bf(uint16_t a, uint16_t b) {
    return (uint32_t)a | ((uint32_t)b << 16);
}
__device__ __forceinline__ uint32_t pk_bf_f(float a, float b) {
    uint32_t r;
    asm("cvt.rn.bf16x2.f32 %0, %2, %1;" : "=r"(r) : "f"(a), "f"(b));
    return r;
}

__device__ __forceinline__ void mma_bf16(float* d, const uint32_t* a, const uint32_t* b) {
    asm volatile(
        "mma.sync.aligned.m16n8k16.row.col.f32.bf16.bf16.f32 "
        "{%0,%1,%2,%3}, {%4,%5,%6,%7}, {%8,%9}, {%0,%1,%2,%3};"
        : "+f"(d[0]), "+f"(d[1]), "+f"(d[2]), "+f"(d[3])
        : "r"(a[0]), "r"(a[1]), "r"(a[2]), "r"(a[3]), "r"(b[0]), "r"(b[1]));
}

__device__ __forceinline__ void cpa16(uint32_t saddr, const void* gaddr) {
    asm volatile("cp.async.cg.shared.global [%0], [%1], 16;" :: "r"(saddr), "l"(gaddr) : "memory");
}
#define CPA_COMMIT() asm volatile("cp.async.commit_group;" ::: "memory")
#define CPA_WAIT0()  asm volatile("cp.async.wait_group 0;" ::: "memory")

__device__ __forceinline__ uint32_t smem_to_u32(const void* p) {
    uint32_t a;
    asm("{ .reg .u64 t; cvta.to.shared.u64 t, %1; cvt.u32.u64 %0, t; }" : "=r"(a) : "l"(p));
    return a;
}

// ---------------- fragment emit ----------------
__device__ __forceinline__ void frag_emit(const float* __restrict__ W, int ldw,
                                          int k0, int n, uint4* dst) {
    float v0 = W[(size_t)k0 * ldw + n];
    float v1 = W[(size_t)(k0 + 1) * ldw + n];
    float v2 = W[(size_t)(k0 + 8) * ldw + n];
    float v3 = W[(size_t)(k0 + 9) * ldw + n];
    uint16_t h0 = bfbits(v0), h1 = bfbits(v1), h2 = bfbits(v2), h3 = bfbits(v3);
    uint16_t q0 = bfbits(v0 - bf2f(h0)), q1 = bfbits(v1 - bf2f(h1));
    uint16_t q2 = bfbits(v2 - bf2f(h2)), q3 = bfbits(v3 - bf2f(h3));
    *dst = make_uint4(pk_bf(h0, h1), pk_bf(h2, h3), pk_bf(q0, q1), pk_bf(q2, q3));
}

// ---------------- launch 0: setup ----------------
__global__ void setup_kernel(const int* __restrict__ ei32,
                             const float* __restrict__ W1, const float* __restrict__ W2,
                             const float* __restrict__ W3, const float* __restrict__ Wih,
                             const float* __restrict__ Whh, const float* __restrict__ decW1,
                             float* counts, float* agg, int Nn, int E, int L) {
    int i = blockIdx.x * blockDim.x + threadIdx.x;
    if (i < Nn) counts[i] = 1.0f;
    if (i < Nn * DD) agg[i] = 0.0f;
    if (i == 0) {
        int probe = (E < 64) ? E : 64;
        int allzero = 1;
        for (int k = 0; k < probe; k++)
            if (ei32[2 * k + 1] != 0) { allzero = 0; break; }
        g_mode = allzero;
    }
    int lane = i & 31;
    int t = i >> 5;
    const int w2t = L * 512, w3t = L * 256, ndt = L * 1280;
    if (t < w2t) {
        int l = t / 512, tile = t % 512;
        int ntl = tile & 7, kt = (tile >> 3) & 15, c = tile >> 7;
        int n = c * 64 + ntl * 8 + (lane >> 2);
        int k0 = kt * 16 + (lane & 3) * 2;
        frag_emit(W2 + (size_t)l * 65536, 256, k0, n,
                  (uint4*)(g_w2img + (size_t)l * 65536 + tile * 128) + lane);
        return;
    }
    t -= w2t;
    if (t < w3t) {
        int l = t / 256, tile = t % 256;
        int ntl = tile & 15, kt2 = (tile >> 4) & 3, c = tile >> 6;
        int n = ntl * 8 + (lane >> 2);
        int k0 = c * 64 + kt2 * 16 + (lane & 3) * 2;
        frag_emit(W3 + (size_t)l * 32768, 128, k0, n,
                  (uint4*)(g_w3img + (size_t)l * 32768 + tile * 128) + lane);
        return;
    }
    t -= w3t;
    if (t < ndt) {
        int l = t / 1280, tile = t % 1280;
        const float* W;
        int N;
        uint32_t* out;
        int toff;
        if (tile < 256)      { W = W1 + (size_t)l * 65536;          N = 256; out = g_nwimg + (size_t)l * 163840;          toff = tile; }
        else if (tile < 512) { W = W1 + (size_t)l * 65536 + 32768;  N = 256; out = g_nwimg + (size_t)l * 163840 + 32768;  toff = tile - 256; }
        else if (tile < 896) { W = Wih + (size_t)l * 49152;         N = 384; out = g_nwimg + (size_t)l * 163840 + 65536;  toff = tile - 512; }
        else                 { W = Whh + (size_t)l * 49152;         N = 384; out = g_nwimg + (size_t)l * 163840 + 114688; toff = tile - 896; }
        int ntl = toff & 15, kt = (toff >> 4) & 7, c = toff >> 7;
        int n = c * 128 + ntl * 8 + (lane >> 2);
        int k0 = kt * 16 + (lane & 3) * 2;
        frag_emit(W, N, k0, n, (uint4*)(out + toff * 128) + lane);
        return;
    }
    t -= ndt;
    if (t < 256) {
        int ntl = t & 15, kt = (t >> 4) & 7, c = t >> 7;
        int n = c * 128 + ntl * 8 + (lane >> 2);
        int k0 = kt * 16 + (lane & 3) * 2;
        frag_emit(decW1, 256, k0, n,
                  (uint4*)(g_nwimg + (size_t)L * 163840 + t * 128) + lane);
    }
}

// ---------------- tiny utility kernels ----------------
__global__ void gru_gate(const float* __restrict__ gi, const float* __restrict__ gh,
                         float* h, float* agg, int Nn) {
    int idx = blockIdx.x * blockDim.x + threadIdx.x;
    if (idx < Nn * DD) {
        int i = idx >> 7, c = idx & 127;
        size_t base = (size_t)i * (3 * DD);
        float r = sigm(gi[base + c] + gh[base + c]);
        float z = sigm(gi[base + DD + c] + gh[base + DD + c]);
        float n = tanhf(gi[base + 2 * DD + c] + r * gh[base + 2 * DD + c]);
        float hv = h[idx];
        h[idx] = (1.0f - z) * n + z * hv;
        agg[idx] = 0.0f;
    }
}
__global__ void dec_final(const float* __restrict__ o2, const float* __restrict__ W3,
                          const float* __restrict__ b3, float* __restrict__ out, int Nn) {
    int gid = blockIdx.x * blockDim.x + threadIdx.x;
    int node = gid >> 5, lane = gid & 31;
    if (node >= Nn) return;
    float s = 0.0f;
    const float* row = o2 + (size_t)node * 256;
#pragma unroll
    for (int j = 0; j < 8; j++) s += row[lane + 32 * j] * W3[lane + 32 * j];
#pragma unroll
    for (int off = 16; off > 0; off >>= 1) s += __shfl_down_sync(0xffffffffu, s, off);
    if (lane == 0) out[node] = s + b3[0];
}

// ---------------- fp32 tiled GEMM (encoder K=16, dec_W2 K=256) ----------------
template <int N, int K, bool DOTANH>
__global__ void gemm_kernel(const float* __restrict__ A, const float* __restrict__ W,
                            const float* __restrict__ bias, float* __restrict__ out, int M) {
    constexpr int BM = 32;
    constexpr int NC = N / 4;
    constexpr int K4 = K / 4;
    constexpr int STR = BM + 2;
    __shared__ float s_a[K * STR];

    const int row0 = blockIdx.x * BM;
    const int tid = threadIdx.x;

    for (int idx = tid; idx < BM * K4; idx += N) {
        int r = idx / K4, k4 = idx % K4;
        float4 v = make_float4(0.f, 0.f, 0.f, 0.f);
        int row = row0 + r;
        if (row < M) v = reinterpret_cast<const float4*>(A)[(size_t)row * K4 + k4];
        s_a[(4 * k4 + 0) * STR + r] = v.x;
        s_a[(4 * k4 + 1) * STR + r] = v.y;
        s_a[(4 * k4 + 2) * STR + r] = v.z;
        s_a[(4 * k4 + 3) * STR + r] = v.w;
    }
    __syncthreads();

    const int colg = tid % NC;
    const int rg = tid / NC;
    const int r0 = rg * 8;

    u64 acc[4][4];
#pragma unroll
    for (int c = 0; c < 4; c++)
#pragma unroll
        for (int p = 0; p < 4; p++) acc[c][p] = 0ull;

    const float4* W4 = reinterpret_cast<const float4*>(W);
    for (int k = 0; k < K; k++) {
        float4 w = W4[(size_t)k * NC + colg];
        u64 w0 = pk2(w.x, w.x), w1 = pk2(w.y, w.y), w2 = pk2(w.z, w.z), w3 = pk2(w.w, w.w);
        const float* srow = &s_a[k * STR + r0];
#pragma unroll
        for (int p = 0; p < 4; p++) {
            u64 m = *reinterpret_cast<const u64*>(srow + 2 * p);
            acc[0][p] = fma2(m, w0, acc[0][p]);
            acc[1][p] = fma2(m, w1, acc[1][p]);
            acc[2][p] = fma2(m, w2, acc[2][p]);
            acc[3][p] = fma2(m, w3, acc[3][p]);
        }
    }

    float4 bv = make_float4(0.f, 0.f, 0.f, 0.f);
    if (bias) bv = reinterpret_cast<const float4*>(bias)[colg];

#pragma unroll
    for (int p = 0; p < 4; p++) {
#pragma unroll
        for (int hh = 0; hh < 2; hh++) {
            int row = row0 + r0 + 2 * p + hh;
            if (row < M) {
                float4 o;
                o.x = (hh ? hi2(acc[0][p]) : lo2(acc[0][p])) + bv.x;
                o.y = (hh ? hi2(acc[1][p]) : lo2(acc[1][p])) + bv.y;
                o.z = (hh ? hi2(acc[2][p]) : lo2(acc[2][p])) + bv.z;
                o.w = (hh ? hi2(acc[3][p]) : lo2(acc[3][p])) + bv.w;
                if (DOTANH) { o.x = tanhf(o.x); o.y = tanhf(o.y); o.z = tanhf(o.z); o.w = tanhf(o.w); }
                reinterpret_cast<float4*>(out)[(size_t)row * NC + colg] = o;
            }
        }
    }
}

// ---------------- split-bf16 mma node GEMM core (R15-proven shape) ----------------
// Runtime meanb3 flag; body identical to the proven gemm_mma.
template <int N, bool DOTANH>
__device__ __forceinline__ void gemm_mma_body(
    const float* __restrict__ A, const uint32_t* __restrict__ Wimg,
    const float* __restrict__ bias, float* __restrict__ out, int M, int bx,
    bool meanb3, const float* __restrict__ counts, const float* __restrict__ cb3,
    char* smem) {
    constexpr int NCH = N / 128;
    uint32_t* ahi = (uint32_t*)smem;
    uint32_t* alo = (uint32_t*)(smem + 32768);
    uint32_t* wb  = (uint32_t*)(smem + 65536);
    float* sbias  = (float*)(smem + 196608);
    const uint32_t sb = smem_to_u32(smem);

    const int tid = threadIdx.x, wid = tid >> 5, lid = tid & 31;
    const int row0 = bx * 128;

    {
        const char* src = (const char*)Wimg + tid * 16;
        uint32_t dst = sb + 65536 + tid * 16;
#pragma unroll
        for (int j = 0; j < 16; j++) cpa16(dst + j * 4096, src + j * 4096);
        CPA_COMMIT();
    }
    for (int i = tid; i < N; i += 256) sbias[i] = bias[i];

    {
        const int e = tid >> 1, half = tid & 1;
        const int row = row0 + e;
        const float4* Ar = reinterpret_cast<const float4*>(A) + (size_t)row * 32 + half * 16;
        const int rb = e * 64;
        const int es = (e & 7) << 2;
        float cn = 1.0f;
        if (meanb3 && row < M) cn = __fdividef(1.0f, counts[row]);
#pragma unroll 4
        for (int i = 0; i < 16; i++) {
            float4 a = (row < M) ? Ar[i] : make_float4(0.f, 0.f, 0.f, 0.f);
            if (meanb3) {
                float4 bv = reinterpret_cast<const float4*>(cb3)[half * 16 + i];
                a.x = a.x * cn + bv.x;
                a.y = a.y * cn + bv.y;
                a.z = a.z * cn + bv.z;
                a.w = a.w * cn + bv.w;
            }
            uint16_t h0 = bfbits(a.x), h1 = bfbits(a.y), h2 = bfbits(a.z), h3 = bfbits(a.w);
            const int w = half * 32 + i * 2;
            const int sw = w ^ es;
            asm volatile("st.shared.v2.b32 [%0], {%1, %2};" ::
                         "r"(sb + (rb + sw) * 4),
                         "r"(pk_bf(h0, h1)), "r"(pk_bf(h2, h3)) : "memory");
            asm volatile("st.shared.v2.b32 [%0], {%1, %2};" ::
                         "r"(sb + 32768 + (rb + sw) * 4),
                         "r"(pk_bf_f(a.x - bf2f(h0), a.y - bf2f(h1))),
                         "r"(pk_bf_f(a.z - bf2f(h2), a.w - bf2f(h3))) : "memory");
        }
    }

    const int g = lid >> 2, q = lid & 3;
    const int r0 = wid * 16 + g;
    const int rowA = r0 * 64, rowB = (r0 + 8) * 64, sswz = g << 2;

    uint32_t ahp[2][4], alp[2][4];

    for (int c = 0; c < NCH; c++) {
        CPA_WAIT0();
        __syncthreads();
        if (c == 0) {
            const int swA = q ^ sswz, swB = (q + 4) ^ sswz;
            ahp[0][0] = ahi[rowA + swA];  ahp[0][1] = ahi[rowB + swA];
            ahp[0][2] = ahi[rowA + swB];  ahp[0][3] = ahi[rowB + swB];
            alp[0][0] = alo[rowA + swA];  alp[0][1] = alo[rowB + swA];
            alp[0][2] = alo[rowA + swB];  alp[0][3] = alo[rowB + swB];
        }
        if (c + 1 < NCH) {
            const char* src = (const char*)(Wimg + (c + 1) * 16384) + tid * 16;
            uint32_t dst = sb + 65536 + ((c + 1) & 1) * 65536 + tid * 16;
#pragma unroll
            for (int j = 0; j < 16; j++) cpa16(dst + j * 4096, src + j * 4096);
            CPA_COMMIT();
        }
        const uint32_t* wc = wb + (c & 1) * 16384;

        float s2[16][4];
#pragma unroll
        for (int n = 0; n < 16; n++)
#pragma unroll
            for (int p = 0; p < 4; p++) s2[n][p] = 0.0f;

        for (int kt = 0; kt < 8; kt++) {
            const int cur = kt & 1;
            {
                const int w0 = ((kt + 1) & 7) * 8 + q;
                const int swA = w0 ^ sswz, swB = (w0 + 4) ^ sswz;
                ahp[cur ^ 1][0] = ahi[rowA + swA];  ahp[cur ^ 1][1] = ahi[rowB + swA];
                ahp[cur ^ 1][2] = ahi[rowA + swB];  ahp[cur ^ 1][3] = ahi[rowB + swB];
                alp[cur ^ 1][0] = alo[rowA + swA];  alp[cur ^ 1][1] = alo[rowB + swA];
                alp[cur ^ 1][2] = alo[rowA + swB];  alp[cur ^ 1][3] = alo[rowB + swB];
            }
#pragma unroll
            for (int nt = 0; nt < 16; nt++) {
                uint4 bb = *reinterpret_cast<const uint4*>(wc + (kt * 16 + nt) * 128 + lid * 4);
                uint32_t bh[2] = {bb.x, bb.y}, bl[2] = {bb.z, bb.w};
                mma_bf16(s2[nt], ahp[cur], bh);
                mma_bf16(s2[nt], alp[cur], bh);
                mma_bf16(s2[nt], ahp[cur], bl);
            }
        }

        const int ra = row0 + r0, rb2 = ra + 8;
#pragma unroll
        for (int nt = 0; nt < 16; nt++) {
            const int col = c * 128 + nt * 8 + 2 * q;
            const float b0v = sbias[col], b1v = sbias[col + 1];
            float o0 = s2[nt][0] + b0v, o1 = s2[nt][1] + b1v;
            float o2v = s2[nt][2] + b0v, o3 = s2[nt][3] + b1v;
            if (DOTANH) { o0 = ftanh(o0); o1 = ftanh(o1); o2v = ftanh(o2v); o3 = ftanh(o3); }
            if (ra < M) *reinterpret_cast<float2*>(out + (size_t)ra * N + col) = make_float2(o0, o1);
            if (rb2 < M) *reinterpret_cast<float2*>(out + (size_t)rb2 * N + col) = make_float2(o2v, o3);
        }
    }
}

// decoder GEMM (N=256, tanh)
__global__ void __launch_bounds__(256, 1)
gemm_mma_dec(const float* __restrict__ A, const uint32_t* __restrict__ Wimg,
             const float* __restrict__ bias, float* __restrict__ out, int M) {
    extern __shared__ char smem[];
    gemm_mma_body<256, true>(A, Wimg, bias, out, M, blockIdx.x, false, nullptr, nullptr, smem);
}

// fused GRU GEMMs: blocks [0,nG) -> gi = (agg/cnt+b3)@Wih+bih; [nG,2nG) -> gh = h@Whh+bhh
__global__ void __launch_bounds__(256, 1)
gemm_gru(const float* __restrict__ agg, const float* __restrict__ h,
         const uint32_t* __restrict__ Wih, const uint32_t* __restrict__ Whh,
         const float* __restrict__ bih, const float* __restrict__ bhh,
         float* __restrict__ gi, float* __restrict__ gh, int M, int nG,
         const float* __restrict__ counts, const float* __restrict__ cb3) {
    extern __shared__ char smem[];
    const bool second = (blockIdx.x >= nG);
    const int bx = second ? blockIdx.x - nG : blockIdx.x;
    if (second)
        gemm_mma_body<384, false>(h, Whh, bhh, gh, M, bx, false, nullptr, nullptr, smem);
    else
        gemm_mma_body<384, false>(agg, Wih, bih, gi, M, bx, true, counts, cb3, smem);
}

// ---------------- gemm_dual: A/B precompute fused + convert ----------------
__global__ void __launch_bounds__(256, 1)
gemm_dual(const float* __restrict__ Ain, const uint32_t* __restrict__ Wimg,
          const float* __restrict__ b1, float* __restrict__ outA, float* __restrict__ outB,
          int M, int nG, const void* __restrict__ ei, float* counts, int E, int do_convert) {
    if (blockIdx.x >= nG) {
        if (!do_convert) return;
        int base = (blockIdx.x - nG) * 2048 + threadIdx.x;
        const int mode = g_mode;
#pragma unroll
        for (int j = 0; j < 8; j++) {
            int e = base + j * 256;
            if (e < E) {
                int s, t;
                if (mode) {
                    const long long* p = (const long long*)ei;
                    s = (int)p[e];
                    t = (int)p[(size_t)E + e];
                } else {
                    const int* p = (const int*)ei;
                    s = p[e];
                    t = p[E + e];
                }
                g_src[e] = s;
                g_tgt[e] = t;
                atomicAdd(&counts[t], 1.0f);
            }
        }
        return;
    }

    extern __shared__ char smem[];
    uint32_t* ahi = (uint32_t*)smem;
    uint32_t* alo = (uint32_t*)(smem + 32768);
    uint32_t* wb  = (uint32_t*)(smem + 65536);
    float* sbias  = (float*)(smem + 196608);
    const uint32_t sb = smem_to_u32(smem);

    const int tid = threadIdx.x, wid = tid >> 5, lid = tid & 31;
    const int row0 = blockIdx.x * 128;

    {
        const char* src = (const char*)Wimg + tid * 16;
        uint32_t dst = sb + 65536 + tid * 16;
#pragma unroll
        for (int j = 0; j < 16; j++) cpa16(dst + j * 4096, src + j * 4096);
        CPA_COMMIT();
    }
    sbias[tid] = b1[tid];

    {
        const int e = tid >> 1, half = tid & 1;
        const int row = row0 + e;
        const float4* Ar = reinterpret_cast<const float4*>(Ain) + (size_t)row * 32 + half * 16;
        const int rb = e * 64;
        const int es = (e & 7) << 2;
#pragma unroll 4
        for (int i = 0; i < 16; i++) {
            float4 a = (row < M) ? Ar[i] : make_float4(0.f, 0.f, 0.f, 0.f);
            uint16_t h0 = bfbits(a.x), h1 = bfbits(a.y), h2 = bfbits(a.z), h3 = bfbits(a.w);
            const int w = half * 32 + i * 2;
            const int sw = w ^ es;
            asm volatile("st.shared.v2.b32 [%0], {%1, %2};" ::
                         "r"(sb + (rb + sw) * 4),
                         "r"(pk_bf(h0, h1)), "r"(pk_bf(h2, h3)) : "memory");
            asm volatile("st.shared.v2.b32 [%0], {%1, %2};" ::
                         "r"(sb + 32768 + (rb + sw) * 4),
                         "r"(pk_bf_f(a.x - bf2f(h0), a.y - bf2f(h1))),
                         "r"(pk_bf_f(a.z - bf2f(h2), a.w - bf2f(h3))) : "memory");
        }
    }

    const int g = lid >> 2, q = lid & 3;
    const int r0 = wid * 16 + g;
    const int rowA = r0 * 64, rowB = (r0 + 8) * 64, sswz = g << 2;

    uint32_t ahp[2][4], alp[2][4];

    for (int c = 0; c < 4; c++) {
        CPA_WAIT0();
        __syncthreads();
        if (c == 0) {
            const int swA = q ^ sswz, swB = (q + 4) ^ sswz;
            ahp[0][0] = ahi[rowA + swA];  ahp[0][1] = ahi[rowB + swA];
            ahp[0][2] = ahi[rowA + swB];  ahp[0][3] = ahi[rowB + swB];
            alp[0][0] = alo[rowA + swA];  alp[0][1] = alo[rowB + swA];
            alp[0][2] = alo[rowA + swB];  alp[0][3] = alo[rowB + swB];
        }
        if (c < 3) {
            const char* src = (const char*)(Wimg + (c + 1) * 16384) + tid * 16;
            uint32_t dst = sb + 65536 + ((c + 1) & 1) * 65536 + tid * 16;
#pragma unroll
            for (int j = 0; j < 16; j++) cpa16(dst + j * 4096, src + j * 4096);
            CPA_COMMIT();
        }
        const uint32_t* wc = wb + (c & 1) * 16384;

        float s2[16][4];
#pragma unroll
        for (int n = 0; n < 16; n++)
#pragma unroll
            for (int p = 0; p < 4; p++) s2[n][p] = 0.0f;

        for (int kt = 0; kt < 8; kt++) {
            const int cur = kt & 1;
            {
                const int w0 = ((kt + 1) & 7) * 8 + q;
                const int swA = w0 ^ sswz, swB = (w0 + 4) ^ sswz;
                ahp[cur ^ 1][0] = ahi[rowA + swA];  ahp[cur ^ 1][1] = ahi[rowB + swA];
                ahp[cur ^ 1][2] = ahi[rowA + swB];  ahp[cur ^ 1][3] = ahi[rowB + swB];
                alp[cur ^ 1][0] = alo[rowA + swA];  alp[cur ^ 1][1] = alo[rowB + swA];
                alp[cur ^ 1][2] = alo[rowA + swB];  alp[cur ^ 1][3] = alo[rowB + swB];
            }
#pragma unroll
            for (int nt = 0; nt < 16; nt++) {
                uint4 bb = *reinterpret_cast<const uint4*>(wc + (kt * 16 + nt) * 128 + lid * 4);
                uint32_t bh[2] = {bb.x, bb.y}, bl[2] = {bb.z, bb.w};
                mma_bf16(s2[nt], ahp[cur], bh);
                mma_bf16(s2[nt], alp[cur], bh);
                mma_bf16(s2[nt], ahp[cur], bl);
            }
        }

        float* out = (c < 2) ? outA : outB;
        const int cc = c & 1;
        const bool addb = (c < 2);
        const int ra = row0 + r0, rb2 = ra + 8;
#pragma unroll
        for (int nt = 0; nt < 16; nt++) {
            const int col = cc * 128 + nt * 8 + 2 * q;
            float b0v = addb ? sbias[col] : 0.0f;
            float b1v = addb ? sbias[col + 1] : 0.0f;
            float o0 = s2[nt][0] + b0v, o1 = s2[nt][1] + b1v;
            float o2v = s2[nt][2] + b0v, o3 = s2[nt][3] + b1v;
            if (ra < M) *reinterpret_cast<float2*>(outA + 0) = *reinterpret_cast<float2*>(outA + 0), // no-op guard removed below
                        *reinterpret_cast<float2*>(out + (size_t)ra * HH + col) = make_float2(o0, o1);
            if (rb2 < M) *reinterpret_cast<float2*>(out + (size_t)rb2 * HH + col) = make_float2(o2v, o3);
        }
    }
}

// ---------------- persistent mma.sync fused edge kernel (R15-proven) ----------------
#define TEM 128
#define SM2_TGT   0
#define SM2_B2    512
#define SM2_M1HI  2048
#define SM2_M1LO  (SM2_M1HI + 65536)
#define SM2_W2    (SM2_M1LO + 65536)
#define SM2_W3    (SM2_W2 + 65536)
#define SM2_TOTAL (SM2_W3 + 32768)       // 231424 bytes

__global__ void __launch_bounds__(256, 1)
edge_mma_kernel(const float* __restrict__ Abuf, const float* __restrict__ Bbuf,
                const uint32_t* __restrict__ w2img, const uint32_t* __restrict__ w3img,
                const float* __restrict__ b2,
                float* __restrict__ agg, int E, int Nn, int ntiles) {
    extern __shared__ char smem[];
    int* s_tgt = (int*)(smem + SM2_TGT);
    float* s_b2 = (float*)(smem + SM2_B2);
    const uint32_t* m1hi = (const uint32_t*)(smem + SM2_M1HI);
    const uint32_t* m1lo = (const uint32_t*)(smem + SM2_M1LO);
    const uint32_t* w2buf = (const uint32_t*)(smem + SM2_W2);
    const uint32_t* w3buf = (const uint32_t*)(smem + SM2_W3);
    const uint32_t sb = smem_to_u32(smem);

    const int tid = threadIdx.x;
    const int wid = tid >> 5, lid = tid & 31;
    const int total = E + Nn;

    {
        const char* src = (const char*)w2img + tid * 16;
        uint32_t dst = sb + SM2_W2 + tid * 16;
#pragma unroll
        for (int j = 0; j < 16; j++) cpa16(dst + j * 4096, src + j * 4096);
        CPA_COMMIT();
    }
    s_b2[tid] = b2[tid];

    const int g = lid >> 2;
    const int q = lid & 3;
    const int r0w = wid * 16 + g;
    const int sswz = g << 2;
    const int rowA = r0w * 128, rowB = (r0w + 8) * 128;

    for (int tile = blockIdx.x; tile < ntiles; tile += gridDim.x) {
        // ---- stage 1: gather + tanh + split ----
        {
            const int e = tid >> 1, half = tid & 1;
            const int eid = tile * TEM + e;
            int si = 0, ti = 0;
            const bool valid = (eid < total);
            if (valid) {
                if (eid < E) { si = g_src[eid]; ti = g_tgt[eid]; }
                else         { si = ti = eid - E; }
            }
            if (half == 0) s_tgt[e] = valid ? ti : -1;
            const float4* Ar = reinterpret_cast<const float4*>(Abuf) + (size_t)ti * 64;
            const float4* Br = reinterpret_cast<const float4*>(Bbuf) + (size_t)si * 64;
            const int rb = e * 128;
            const int es = (e & 7) << 2;
#pragma unroll 8
            for (int i = 0; i < 32; i++) {
                float4 a = Ar[half * 32 + i], b = Br[half * 32 + i];
                float v0 = ftanh(a.x + b.x), v1 = ftanh(a.y + b.y);
                float v2 = ftanh(a.z + b.z), v3 = ftanh(a.w + b.w);
                uint16_t h0 = bfbits(v0), h1 = bfbits(v1), h2 = bfbits(v2), h3 = bfbits(v3);
                const int w = half * 64 + i * 2;
                const int sw = w ^ es;
                asm volatile("st.shared.v2.b32 [%0], {%1, %2};" ::
                             "r"(sb + SM2_M1HI + (rb + sw) * 4),
                             "r"(pk_bf(h0, h1)), "r"(pk_bf(h2, h3)) : "memory");
                asm volatile("st.shared.v2.b32 [%0], {%1, %2};" ::
                             "r"(sb + SM2_M1LO + (rb + sw) * 4),
                             "r"(pk_bf_f(v0 - bf2f(h0), v1 - bf2f(h1))),
                             "r"(pk_bf_f(v2 - bf2f(h2), v3 - bf2f(h3))) : "memory");
            }
        }

        float m3[16][4];
#pragma unroll
        for (int n = 0; n < 16; n++)
#pragma unroll
            for (int p = 0; p < 4; p++) m3[n][p] = 0.0f;

        int tg0 = -1, tg1 = -1;
        uint32_t ahf[2][4], alf[2][4];

        for (int c = 0; c < 4; c++) {
            CPA_WAIT0();
            __syncthreads();

            if (c == 0) {
                tg0 = s_tgt[r0w];
                tg1 = s_tgt[r0w + 8];
                const int swA = q ^ sswz, swB = (q + 4) ^ sswz;
                ahf[0][0] = m1hi[rowA + swA];  ahf[0][1] = m1hi[rowB + swA];
                ahf[0][2] = m1hi[rowA + swB];  ahf[0][3] = m1hi[rowB + swB];
                alf[0][0] = m1lo[rowA + swA];  alf[0][1] = m1lo[rowB + swA];
                alf[0][2] = m1lo[rowA + swB];  alf[0][3] = m1lo[rowB + swB];
            }

            // prefetch W3 chunk c (overlaps stage 2)
            {
                const char* src = (const char*)(w3img + c * 8192) + tid * 16;
                uint32_t dst = sb + SM2_W3 + tid * 16;
#pragma unroll
                for (int j = 0; j < 8; j++) cpa16(dst + j * 4096, src + j * 4096);
                CPA_COMMIT();
            }

            // ---- stage 2 ----
            float s2[8][4];
#pragma unroll
            for (int n = 0; n < 8; n++)
#pragma unroll
                for (int p = 0; p < 4; p++) s2[n][p] = 0.0f;

            for (int kt = 0; kt < 16; kt++) {
                const int cur = kt & 1;
                {
                    const int w0 = ((kt + 1) & 15) * 8 + q;
                    const int swA = w0 ^ sswz, swB = (w0 + 4) ^ sswz;
                    ahf[cur ^ 1][0] = m1hi[rowA + swA];  ahf[cur ^ 1][1] = m1hi[rowB + swA];
                    ahf[cur ^ 1][2] = m1hi[rowA + swB];  ahf[cur ^ 1][3] = m1hi[rowB + swB];
                    alf[cur ^ 1][0] = m1lo[rowA + swA];  alf[cur ^ 1][1] = m1lo[rowB + swA];
                    alf[cur ^ 1][2] = m1lo[rowA + swB];  alf[cur ^ 1][3] = m1lo[rowB + swB];
                }
#pragma unroll
                for (int nt = 0; nt < 8; nt++) {
                    uint4 bb = *reinterpret_cast<const uint4*>(
                        w2buf + (kt * 8 + nt) * 128 + lid * 4);
                    uint32_t bhi[2] = {bb.x, bb.y}, blo[2] = {bb.z, bb.w};
                    mma_bf16(s2[nt], ahf[cur], bhi);
                    mma_bf16(s2[nt], alf[cur], bhi);
                    mma_bf16(s2[nt], ahf[cur], blo);
                }
            }

            // ---- epilogue ----
            uint32_t a2hi[4][4], a2lo[4][4];
#pragma unroll
            for (int nt = 0; nt < 8; nt++) {
                const int colbase = c * 64 + nt * 8 + 2 * q;
                const float b0v = s_b2[colbase], b1v = s_b2[colbase + 1];
                float v0 = ftanh(s2[nt][0] + b0v), v1 = ftanh(s2[nt][1] + b1v);
                float v2 = ftanh(s2[nt][2] + b0v), v3 = ftanh(s2[nt][3] + b1v);
                uint16_t h0 = bfbits(v0), h1 = bfbits(v1), h2 = bfbits(v2), h3 = bfbits(v3);
                const int t2 = nt >> 1, ko = (nt & 1) * 2;
                a2hi[t2][ko + 0] = pk_bf(h0, h1);
                a2hi[t2][ko + 1] = pk_bf(h2, h3);
                a2lo[t2][ko + 0] = pk_bf_f(v0 - bf2f(h0), v1 - bf2f(h1));
                a2lo[t2][ko + 1] = pk_bf_f(v2 - bf2f(h2), v3 - bf2f(h3));
            }

            CPA_WAIT0();
            __syncthreads();

            // prefetch W2 next chunk (wraps to chunk 0 for the next tile)
            if (c < 3 || tile + gridDim.x < ntiles) {
                const int cn = (c + 1) & 3;
                const char* src = (const char*)(w2img + cn * 16384) + tid * 16;
                uint32_t dst = sb + SM2_W2 + tid * 16;
#pragma unroll
                for (int j = 0; j < 16; j++) cpa16(dst + j * 4096, src + j * 4096);
                CPA_COMMIT();
            }

            // ---- stage 3 ----
            for (int kt2 = 0; kt2 < 4; kt2++) {
#pragma unroll
                for (int nt = 0; nt < 16; nt++) {
                    uint4 bb = *reinterpret_cast<const uint4*>(
                        w3buf + (kt2 * 16 + nt) * 128 + lid * 4);
                    uint32_t bhi[2] = {bb.x, bb.y}, blo[2] = {bb.z, bb.w};
                    mma_bf16(m3[nt], a2hi[kt2], bhi);
                    mma_bf16(m3[nt], a2lo[kt2], bhi);
                    mma_bf16(m3[nt], a2hi[kt2], blo);
                }
            }
        }

        // ---- scatter ----
        if (tg0 >= 0) {
            float2* base = reinterpret_cast<float2*>(agg + (size_t)tg0 * DD + 2 * q);
#pragma unroll
            for (int nt = 0; nt < 16; nt++)
                atomicAdd(base + nt * 4, make_float2(m3[nt][0], m3[nt][1]));
        }
        if (tg1 >= 0) {
            float2* base = reinterpret_cast<float2*>(agg + (size_t)tg1 * DD + 2 * q);
#pragma unroll
            for (int nt = 0; nt < 16; nt++)
                atomicAdd(base + nt * 4, make_float2(m3[nt][2], m3[nt][3]));
        }
    }
}

// ---------------- host launcher ----------------
extern "C" void kernel_launch(void* const* d_in, const int* in_sizes, int n_in,
                              void* d_out, int out_size) {
    const float* x      = (const float*)d_in[0];
    const void*  ei     = d_in[1];
    const float* enc_W  = (const float*)d_in[2];
    const float* enc_b  = (const float*)d_in[3];
    const float* msg_W1 = (const float*)d_in[4];
    const float* msg_b1 = (const float*)d_in[5];
    const float* msg_W2 = (const float*)d_in[6];
    const float* msg_b2 = (const float*)d_in[7];
    const float* msg_W3 = (const float*)d_in[8];
    const float* msg_b3 = (const float*)d_in[9];
    const float* gru_Wih = (const float*)d_in[10];
    const float* gru_Whh = (const float*)d_in[11];
    const float* gru_bih = (const float*)d_in[12];
    const float* gru_bhh = (const float*)d_in[13];
    const float* dec_W1 = (const float*)d_in[14];
    const float* dec_b1 = (const float*)d_in[15];
    const float* dec_W2 = (const float*)d_in[16];
    const float* dec_b2 = (const float*)d_in[17];
    const float* dec_W3 = (const float*)d_in[18];
    const float* dec_b3 = (const float*)d_in[19];

    const int Nn = in_sizes[0] / 16;
    const int E  = in_sizes[1] / 2;
    const int L  = in_sizes[4] / (2 * DD * HH);

    float *h, *A, *B, *agg, *gi, *gh, *counts;
    uint32_t *w2img, *w3img, *nwimg;
    cudaGetSymbolAddress((void**)&h, g_h);
    cudaGetSymbolAddress((void**)&A, g_A);
    cudaGetSymbolAddress((void**)&B, g_B);
    cudaGetSymbolAddress((void**)&agg, g_agg);
    cudaGetSymbolAddress((void**)&gi, g_gi);
    cudaGetSymbolAddress((void**)&gh, g_gh);
    cudaGetSymbolAddress((void**)&counts, g_counts);
    cudaGetSymbolAddress((void**)&w2img, g_w2img);
    cudaGetSymbolAddress((void**)&w3img, g_w3img);
    cudaGetSymbolAddress((void**)&nwimg, g_nwimg);

    cudaFuncSetAttribute(edge_mma_kernel, cudaFuncAttributeMaxDynamicSharedMemorySize,
                         SM2_TOTAL);
    cudaFuncSetAttribute(gemm_dual, cudaFuncAttributeMaxDynamicSharedMemorySize,
                         196608 + 1024);
    cudaFuncSetAttribute(gemm_mma_dec, cudaFuncAttributeMaxDynamicSharedMemorySize,
                         196608 + 256 * 4);
    cudaFuncSetAttribute(gemm_gru, cudaFuncAttributeMaxDynamicSharedMemorySize,
                         196608 + 384 * 4);

    int dev = 0;
    cudaGetDevice(&dev);
    int nsm = 148;
    cudaDeviceGetAttribute(&nsm, cudaDevAttrMultiProcessorCount, dev);

    const int gM = (Nn + 31) / 32;
    const int gM2 = (Nn + 127) / 128;
    const int ntiles = (E + Nn + TEM - 1) / TEM;
    const int nConv = (E + 2047) / 2048;
    const int smn256 = 196608 + 256 * 4;
    const int smn384 = 196608 + 384 * 4;
    const int smdual = 196608 + 1024;

    setup_kernel<<<(Nn * DD + 255) / 256, 256>>>(
        (const int*)ei, msg_W1, msg_W2, msg_W3, gru_Wih, gru_Whh, dec_W1,
        counts, agg, Nn, E, L);
    gemm_kernel<128, 16, true><<<gM, 128>>>(x, enc_W, enc_b, h, Nn);

    for (int l = 0; l < L; l++) {
        const uint32_t* img = nwimg + (size_t)l * 163840;
        const float* b1l = msg_b1 + (size_t)l * HH;
        const float* b2l = msg_b2 + (size_t)l * HH;
        const float* b3l = msg_b3 + (size_t)l * DD;
        const float* bih = gru_bih + (size_t)l * 3 * DD;
        const float* bhh = gru_bhh + (size_t)l * 3 * DD;

        gemm_dual<<<gM2 + nConv, 256, smdual>>>(
            h, img, b1l, A, B, Nn, gM2, ei, counts, E, l == 0 ? 1 : 0);

        edge_mma_kernel<<<nsm, 256, SM2_TOTAL>>>(
            A, B, w2img + (size_t)l * 65536, w3img + (size_t)l * 32768,
            b2l, agg, E, Nn, ntiles);

        // fused gi+gh GEMMs (one launch, tail waves overlap)
        gemm_gru<<<2 * gM2, 256, smn384>>>(agg, h, img + 65536, img + 114688,
                                           bih, bhh, gi, gh, Nn, gM2, counts, b3l);

        gru_gate<<<(Nn * DD + 255) / 256, 256>>>(gi, gh, h, agg, Nn);
    }

    gemm_mma_dec<<<gM2, 256, smn256>>>(h, nwimg + (size_t)L * 163840, dec_b1, A, Nn);
    gemm_kernel<256, 256, true><<<gM, 256>>>(A, dec_W2, dec_b2, B, Nn);
    dec_final<<<(Nn + 7) / 8, 256>>>(B, dec_W3, dec_b3, (float*)d_out, Nn);
}